// round 2
// baseline (speedup 1.0000x reference)
#include <cuda_runtime.h>
#include <cuda_bf16.h>
#include <math.h>

// RankingLoss: B=65536 rows, C=1024 classes, float32 scores, int32 labels
// (JAX silently downgrades the requested int64 to int32 with x64 disabled).
// loss = mean_b [ log1p(exp(2*(2.5 - s_pos))) + log1p(exp(2*(0.5 + s_neg))) ]
//   s_pos = scores[b, label[b]]
//   s_neg = max_{c != label} scores[b,c]   (0 if label == 0)

#define NUM_B 65536
#define NUM_C 1024
#define WARPS_PER_BLOCK 8

__device__ double g_acc = 0.0;
__device__ unsigned int g_done = 0;

__device__ __forceinline__ float softplus_g(float t) {
    // log1p(exp(t)) with overflow guard
    return (t > 20.0f) ? t : log1pf(__expf(t));
}

__global__ void __launch_bounds__(WARPS_PER_BLOCK * 32)
ranking_loss_kernel(const float* __restrict__ scores,
                    const int* __restrict__ labels,
                    float* __restrict__ out)
{
    const int lane = threadIdx.x & 31;
    const int warp = threadIdx.x >> 5;
    const int row  = blockIdx.x * WARPS_PER_BLOCK + warp;

    const int lbl = labels[row];

    const float4* __restrict__ rp =
        (const float4*)(scores + (size_t)row * NUM_C);

    float vmax = -INFINITY;   // max over non-label columns (this lane's slice)
    float spos = -INFINITY;   // label column value (only owning lane sets it)

    // 32 lanes * 8 float4 = 1024 floats = one row. Coalesced, MLP=8.
    #pragma unroll
    for (int w = 0; w < 8; ++w) {
        const int f4 = w * 32 + lane;      // float4 index within row
        const float4 v = rp[f4];
        const int col = f4 * 4;

        float a0 = v.x, a1 = v.y, a2 = v.z, a3 = v.w;
        if (col + 0 == lbl) { spos = a0; a0 = -INFINITY; }
        if (col + 1 == lbl) { spos = a1; a1 = -INFINITY; }
        if (col + 2 == lbl) { spos = a2; a2 = -INFINITY; }
        if (col + 3 == lbl) { spos = a3; a3 = -INFINITY; }
        vmax = fmaxf(vmax, fmaxf(fmaxf(a0, a1), fmaxf(a2, a3)));
    }

    // Warp tree reduction: max for vmax, max for spos (only one lane holds it).
    #pragma unroll
    for (int o = 16; o > 0; o >>= 1) {
        vmax = fmaxf(vmax, __shfl_xor_sync(0xffffffffu, vmax, o));
        spos = fmaxf(spos, __shfl_xor_sync(0xffffffffu, spos, o));
    }

    float row_loss = 0.0f;
    if (lane == 0) {
        const float s_neg = (lbl == 0) ? 0.0f : vmax;
        const float lp = softplus_g(2.0f * (2.5f - spos));
        const float ln = softplus_g(2.0f * (0.5f + s_neg));
        row_loss = lp + ln;
    }

    // Block reduction of the 8 per-warp row losses.
    __shared__ float s_part[WARPS_PER_BLOCK];
    if (lane == 0) s_part[warp] = row_loss;
    __syncthreads();

    if (threadIdx.x == 0) {
        float blk = 0.0f;
        #pragma unroll
        for (int i = 0; i < WARPS_PER_BLOCK; ++i) blk += s_part[i];
        atomicAdd(&g_acc, (double)blk);
        __threadfence();
        const unsigned int ticket = atomicAdd(&g_done, 1u);
        if (ticket == gridDim.x - 1) {
            // Last block: publish mean, reset state for next (graph-replayed) call.
            *out = (float)(g_acc / (double)NUM_B);
            g_acc = 0.0;
            g_done = 0;
        }
    }
}

extern "C" void kernel_launch(void* const* d_in, const int* in_sizes, int n_in,
                              void* d_out, int out_size)
{
    const float* scores = (const float*)d_in[0];
    const int*   labels = (const int*)d_in[1];
    float*       out    = (float*)d_out;

    const int grid = NUM_B / WARPS_PER_BLOCK;   // 8192
    ranking_loss_kernel<<<grid, WARPS_PER_BLOCK * 32>>>(scores, labels, out);
}